// round 7
// baseline (speedup 1.0000x reference)
#include <cuda_runtime.h>
#include <cuda_bf16.h>
#include <cstdint>
#include <cstddef>

#define B_   4
#define T_   448
#define TPAD 512
#define U_   448
#define SKS_ 96
#define BKS_ 32
#define H_   96
#define V_   128
#define PITCH 208         // smem row pitch (bytes) for 96 bf16 + pad -> conflict-free ldmatrix

// ---------------- device scratch ----------------
__device__ unsigned short g_shhi[B_ * TPAD * H_];   // bf16 hi of sh
__device__ unsigned short g_shlo[B_ * TPAD * H_];   // bf16 lo of sh
__device__ float g_rbh[B_ * U_ * H_];               // relu(bh), fp32

// ---------------- asm helpers ----------------
__device__ __forceinline__ uint32_t smem_u32(const void* p) {
    uint32_t a;
    asm("{ .reg .u64 t; cvta.to.shared.u64 t, %1; cvt.u32.u64 %0, t; }" : "=r"(a) : "l"(p));
    return a;
}
#define LDSM4(r, addr) \
    asm volatile("ldmatrix.sync.aligned.m8n8.x4.shared.b16 {%0,%1,%2,%3}, [%4];" \
        : "=r"((r)[0]), "=r"((r)[1]), "=r"((r)[2]), "=r"((r)[3]) : "r"(addr))

#define MMA16816(c, a0, a1, a2, a3, b0, b1) \
    asm volatile("mma.sync.aligned.m16n8k16.row.col.f32.bf16.bf16.f32 " \
        "{%0,%1,%2,%3}, {%4,%5,%6,%7}, {%8,%9}, {%0,%1,%2,%3};" \
        : "+f"((c)[0]), "+f"((c)[1]), "+f"((c)[2]), "+f"((c)[3]) \
        : "r"(a0), "r"(a1), "r"(a2), "r"(a3), "r"(b0), "r"(b1))

__device__ __forceinline__ uint32_t pack2bf(float a, float b) {
    __nv_bfloat162 h = __floats2bfloat162_rn(a, b);
    return *reinterpret_cast<uint32_t*>(&h);
}
__device__ __forceinline__ void split2(float z0, float z1, uint32_t& hi, uint32_t& lo) {
    __nv_bfloat162 h = __floats2bfloat162_rn(z0, z1);
    hi = *reinterpret_cast<uint32_t*>(&h);
    lo = pack2bf(z0 - __bfloat162float(h.x), z1 - __bfloat162float(h.y));
}

// ============================================================================
// Input projections; sh written as bf16 hi/lo split (A operand precomputation).
// ============================================================================
__global__ __launch_bounds__(96) void proj8(
    const float* __restrict__ s,   const float* __restrict__ bmat,
    const float* __restrict__ Wsh, const float* __restrict__ bsh,
    const float* __restrict__ Wbh, const float* __restrict__ bbh)
{
    __shared__ float sw[H_ * 97];
    __shared__ float srow[8][97];
    const int h = threadIdx.x;

    if (blockIdx.y == 0) {
        for (int i = h; i < H_ * SKS_; i += 96)
            sw[(i / SKS_) * 97 + (i % SKS_)] = Wsh[i];
        const int base = blockIdx.x * 8;
        #pragma unroll
        for (int r = 0; r < 8; r++) {
            int row = base + r, b = row >> 9, t = row & 511;
            srow[r][h] = (t < T_) ? s[((size_t)b * T_ + t) * SKS_ + h] : 0.0f;
        }
        __syncthreads();
        float acc[8];
        const float bias = bsh[h];
        #pragma unroll
        for (int r = 0; r < 8; r++) acc[r] = bias;
        #pragma unroll 4
        for (int k = 0; k < SKS_; k++) {
            float w = sw[h * 97 + k];
            #pragma unroll
            for (int r = 0; r < 8; r++) acc[r] = fmaf(srow[r][k], w, acc[r]);
        }
        #pragma unroll
        for (int r = 0; r < 8; r++) {
            __nv_bfloat16 hi = __float2bfloat16(acc[r]);
            float lo = acc[r] - __bfloat162float(hi);
            __nv_bfloat16 lob = __float2bfloat16(lo);
            g_shhi[(size_t)(base + r) * H_ + h] = *reinterpret_cast<unsigned short*>(&hi);
            g_shlo[(size_t)(base + r) * H_ + h] = *reinterpret_cast<unsigned short*>(&lob);
        }
    } else {
        if (blockIdx.x >= (B_ * U_) / 8) return;
        for (int i = h; i < H_ * BKS_; i += 96)
            sw[(i / BKS_) * 33 + (i % BKS_)] = Wbh[i];
        const int base = blockIdx.x * 8;
        if (h < BKS_) {
            #pragma unroll
            for (int r = 0; r < 8; r++)
                srow[r][h] = bmat[(size_t)(base + r) * BKS_ + h];
        }
        __syncthreads();
        float acc[8];
        const float bias = bbh[h];
        #pragma unroll
        for (int r = 0; r < 8; r++) acc[r] = bias;
        #pragma unroll
        for (int k = 0; k < BKS_; k++) {
            float w = sw[h * 33 + k];
            #pragma unroll
            for (int r = 0; r < 8; r++) acc[r] = fmaf(srow[r][k], w, acc[r]);
        }
        #pragma unroll
        for (int r = 0; r < 8; r++) g_rbh[(size_t)(base + r) * H_ + h] = fmaxf(acc[r], 0.0f);
    }
}

// ============================================================================
// Main kernel. grid (18, 16): blockIdx.y = (b, t0) group (A staged ONCE per
// CTA), blockIdx.x = u-range. Per item: B' = rbh*W computed fp32 -> bf16
// hi/lo into smem; MMA loop is LDSM+MMA only (no LDG). Bias in epilogue.
// Warp: mg = wid>>1 -> rows mg*32..+31, ng = wid&1 -> cols ng*64..+63.
// ============================================================================
#define S_AHI 0
#define S_ALO 26624
#define S_BHI 53248
#define S_BLO 79872
#define S_RED 106496               // [128][2] float2
#define S_RBH 108544               // [96] float
#define S_BIA 109056               // [128] float
#define SMEM_MAIN 109568

__global__ __launch_bounds__(256, 2) void joiner_hmma(
    const float* __restrict__ Wout, const float* __restrict__ bout,
    float* __restrict__ out)
{
    extern __shared__ __align__(16) char smem[];
    const uint32_t sb = smem_u32(smem);
    const int tid = threadIdx.x;
    const int wid = tid >> 5, lid = tid & 31;
    const int mg = wid >> 1, ng = wid & 1;
    const int n0 = ng * 64;
    const int q  = lid >> 2, qe = lid & 3;

    const int g  = blockIdx.y;
    const int t0 = (g & 3) * 128;
    const int bz = g >> 2;
    const int c  = blockIdx.x;                       // 0..17
    const int ustart = c * 24 + (c < 16 ? c : 16);   // 25,25,...(x16),24,24
    const int ucnt   = 24 + (c < 16 ? 1 : 0);

    // ---- one-time: stage bias + A hi/lo tile (t0..t0+127) ----
    if (tid < V_) ((float*)(smem + S_BIA))[tid] = bout[tid];
    {
        const uint32_t* shi = (const uint32_t*)g_shhi + ((size_t)(bz * TPAD) + t0) * 48;
        const uint32_t* slo = (const uint32_t*)g_shlo + ((size_t)(bz * TPAD) + t0) * 48;
        for (int i = tid; i < 128 * 48; i += 256) {
            const int row = i / 48, kp = i - row * 48;
            *(uint32_t*)(smem + S_AHI + row * PITCH + kp * 4) = shi[row * 48 + kp];
            *(uint32_t*)(smem + S_ALO + row * PITCH + kp * 4) = slo[row * 48 + kp];
        }
    }

    // ldmatrix lane addresses
    const uint32_t aoff = (uint32_t)((lid & 15) * PITCH + (lid >> 4) * 16);
    const uint32_t boff = (uint32_t)(((lid & 7) + ((lid >> 4) << 3)) * PITCH + ((lid >> 3) & 1) * 16);
    const uint32_t sAh = sb + S_AHI + (uint32_t)(mg * 32 * PITCH) + aoff;
    const uint32_t sAl = sb + S_ALO + (uint32_t)(mg * 32 * PITCH) + aoff;
    const uint32_t sBh = sb + S_BHI + (uint32_t)(n0 * PITCH) + boff;
    const uint32_t sBl = sb + S_BLO + (uint32_t)(n0 * PITCH) + boff;

    float2* red = (float2*)(smem + S_RED);
    float*  rbF = (float*)(smem + S_RBH);
    const float* biaL = (const float*)(smem + S_BIA) + n0 + 2 * qe;

    // B'-prep assignment: v = tid>>1, k-half = (tid&1)*48
    const int pv = tid >> 1;
    const int pk = (tid & 1) * 48;
    const float* Wrow = Wout + pv * H_ + pk;
    char* bhiW = smem + S_BHI + pv * PITCH + pk * 2;
    char* bloW = smem + S_BLO + pv * PITCH + pk * 2;

    for (int it = 0; it < ucnt; it++) {
        const int u = ustart + it;

        __syncthreads();   // previous item fully consumed (B', red)

        if (tid < H_) rbF[tid] = g_rbh[((size_t)bz * U_ + u) * H_ + tid];
        __syncthreads();

        // ---- B'-prep: B'[v,k] = rbh[k]*W[v,k], split bf16 hi/lo to smem ----
        #pragma unroll
        for (int i = 0; i < 12; i++) {
            float4 wv = *(const float4*)(Wrow + 4 * i);
            float4 rv = *(const float4*)(rbF + pk + 4 * i);
            uint32_t h0, l0, h1, l1;
            split2(wv.x * rv.x, wv.y * rv.y, h0, l0);
            split2(wv.z * rv.z, wv.w * rv.w, h1, l1);
            *(uint2*)(bhiW + 8 * i) = make_uint2(h0, h1);
            *(uint2*)(bloW + 8 * i) = make_uint2(l0, l1);
        }
        __syncthreads();

        // ---- MMA: 3 products x 6 k-steps, all operands via LDSM ----
        float acc[2][8][4];
        #pragma unroll
        for (int i = 0; i < 2; i++)
            #pragma unroll
            for (int j = 0; j < 8; j++)
                #pragma unroll
                for (int e4 = 0; e4 < 4; e4++) acc[i][j][e4] = 0.0f;

        #pragma unroll
        for (int s = 0; s < 6; s++) {
            uint32_t ah[2][4], al[2][4], bq[4][4];
            LDSM4(ah[0], sAh + s * 32);
            LDSM4(ah[1], sAh + 16 * PITCH + s * 32);
            LDSM4(al[0], sAl + s * 32);
            LDSM4(al[1], sAl + 16 * PITCH + s * 32);
            #pragma unroll
            for (int jj = 0; jj < 4; jj++)
                LDSM4(bq[jj], sBh + jj * 16 * PITCH + s * 32);
            #pragma unroll
            for (int i = 0; i < 2; i++)
                #pragma unroll
                for (int j = 0; j < 8; j++)
                    MMA16816(acc[i][j], ah[i][0], ah[i][1], ah[i][2], ah[i][3],
                             bq[j >> 1][(j & 1) * 2], bq[j >> 1][(j & 1) * 2 + 1]);
            #pragma unroll
            for (int i = 0; i < 2; i++)
                #pragma unroll
                for (int j = 0; j < 8; j++)
                    MMA16816(acc[i][j], al[i][0], al[i][1], al[i][2], al[i][3],
                             bq[j >> 1][(j & 1) * 2], bq[j >> 1][(j & 1) * 2 + 1]);
            #pragma unroll
            for (int jj = 0; jj < 4; jj++)
                LDSM4(bq[jj], sBl + jj * 16 * PITCH + s * 32);
            #pragma unroll
            for (int i = 0; i < 2; i++)
                #pragma unroll
                for (int j = 0; j < 8; j++)
                    MMA16816(acc[i][j], ah[i][0], ah[i][1], ah[i][2], ah[i][3],
                             bq[j >> 1][(j & 1) * 2], bq[j >> 1][(j & 1) * 2 + 1]);
        }

        // ---- bias add (same pair for both row-halves) ----
        #pragma unroll
        for (int j = 0; j < 8; j++) {
            float2 bv = *(const float2*)(biaL + 8 * j);
            #pragma unroll
            for (int i = 0; i < 2; i++) {
                acc[i][j][0] += bv.x; acc[i][j][1] += bv.y;
                acc[i][j][2] += bv.x; acc[i][j][3] += bv.y;
            }
        }

        // ---- epilogue: log-softmax over V=128 (two warps share each row) ----
        float mx[2][2], sm[2][2];
        #pragma unroll
        for (int i = 0; i < 2; i++)
            #pragma unroll
            for (int h = 0; h < 2; h++) {
                float m = -3.4e38f;
                #pragma unroll
                for (int j = 0; j < 8; j++) {
                    m = fmaxf(m, acc[i][j][2 * h]);
                    m = fmaxf(m, acc[i][j][2 * h + 1]);
                }
                m = fmaxf(m, __shfl_xor_sync(0xffffffffu, m, 1));
                m = fmaxf(m, __shfl_xor_sync(0xffffffffu, m, 2));
                float ss = 0.0f;
                #pragma unroll
                for (int j = 0; j < 8; j++)
                    ss += __expf(acc[i][j][2 * h] - m) + __expf(acc[i][j][2 * h + 1] - m);
                ss += __shfl_xor_sync(0xffffffffu, ss, 1);
                ss += __shfl_xor_sync(0xffffffffu, ss, 2);
                mx[i][h] = m; sm[i][h] = ss;
            }
        if (qe == 0) {
            #pragma unroll
            for (int i = 0; i < 2; i++)
                #pragma unroll
                for (int h = 0; h < 2; h++)
                    red[(mg * 32 + i * 16 + h * 8 + q) * 2 + ng] = make_float2(mx[i][h], sm[i][h]);
        }
        __syncthreads();

        #pragma unroll
        for (int i = 0; i < 2; i++)
            #pragma unroll
            for (int h = 0; h < 2; h++) {
                const int rloc = i * 16 + h * 8 + q;
                const int t = t0 + mg * 32 + rloc;
                if (t >= T_) continue;
                float2 o = red[(mg * 32 + rloc) * 2 + (ng ^ 1)];
                float M = fmaxf(mx[i][h], o.x);
                float S = sm[i][h] * __expf(mx[i][h] - M) + o.y * __expf(o.x - M);
                float lse = M + __logf(S);
                float2* op = (float2*)(out + (((size_t)bz * T_ + t) * U_ + u) * V_ + n0 + qe * 2);
                #pragma unroll
                for (int j = 0; j < 8; j++) {
                    float2 v;
                    v.x = acc[i][j][2 * h]     - lse;
                    v.y = acc[i][j][2 * h + 1] - lse;
                    op[4 * j] = v;
                }
            }
    }
}

extern "C" void kernel_launch(void* const* d_in, const int* in_sizes, int n_in,
                              void* d_out, int out_size)
{
    (void)in_sizes; (void)n_in; (void)out_size;
    const float* s    = (const float*)d_in[0];
    const float* bmat = (const float*)d_in[1];
    const float* Wsh  = (const float*)d_in[2];
    const float* bsh  = (const float*)d_in[3];
    const float* Wbh  = (const float*)d_in[4];
    const float* bbh  = (const float*)d_in[5];
    const float* Wout = (const float*)d_in[6];
    const float* bout = (const float*)d_in[7];
    float* out = (float*)d_out;

    cudaFuncSetAttribute(joiner_hmma,
                         cudaFuncAttributeMaxDynamicSharedMemorySize, SMEM_MAIN);

    proj8<<<dim3((B_ * TPAD) / 8, 2), 96>>>(s, bmat, Wsh, bsh, Wbh, bbh);
    joiner_hmma<<<dim3(18, 16), 256, SMEM_MAIN>>>(Wout, bout, out);
}

// round 8
// speedup vs baseline: 1.6430x; 1.6430x over previous
#include <cuda_runtime.h>
#include <cuda_fp16.h>
#include <cstdint>
#include <cstddef>

#define B_   4
#define T_   448
#define TPAD 512
#define U_   448
#define SKS_ 96
#define BKS_ 32
#define H_   96
#define V_   128
#define PITCH 208         // smem B row pitch (96 fp16 = 192 B + pad) -> conflict-free ldmatrix

// ---------------- device scratch ----------------
__device__ float g_sh [B_ * TPAD * H_];
__device__ float g_rbh[B_ * U_ * H_];

// ---------------- asm helpers ----------------
__device__ __forceinline__ uint32_t smem_u32(const void* p) {
    uint32_t a;
    asm("{ .reg .u64 t; cvta.to.shared.u64 t, %1; cvt.u32.u64 %0, t; }" : "=r"(a) : "l"(p));
    return a;
}
#define LDSM4(r, addr) \
    asm volatile("ldmatrix.sync.aligned.m8n8.x4.shared.b16 {%0,%1,%2,%3}, [%4];" \
        : "=r"((r)[0]), "=r"((r)[1]), "=r"((r)[2]), "=r"((r)[3]) : "r"(addr))

#define MMA16816(c, a0, a1, a2, a3, b0, b1) \
    asm volatile("mma.sync.aligned.m16n8k16.row.col.f32.f16.f16.f32 " \
        "{%0,%1,%2,%3}, {%4,%5,%6,%7}, {%8,%9}, {%0,%1,%2,%3};" \
        : "+f"((c)[0]), "+f"((c)[1]), "+f"((c)[2]), "+f"((c)[3]) \
        : "r"(a0), "r"(a1), "r"(a2), "r"(a3), "r"(b0), "r"(b1))

__device__ __forceinline__ uint32_t packh2(float a, float b) {
    __half2 h = __floats2half2_rn(a, b);
    return *reinterpret_cast<uint32_t*>(&h);
}

// ============================================================================
// Input projections (R6 version: fp32 outputs).
// ============================================================================
__global__ __launch_bounds__(96) void proj8(
    const float* __restrict__ s,   const float* __restrict__ bmat,
    const float* __restrict__ Wsh, const float* __restrict__ bsh,
    const float* __restrict__ Wbh, const float* __restrict__ bbh)
{
    __shared__ float sw[H_ * 97];
    __shared__ float srow[8][97];
    const int h = threadIdx.x;

    if (blockIdx.y == 0) {
        for (int i = h; i < H_ * SKS_; i += 96)
            sw[(i / SKS_) * 97 + (i % SKS_)] = Wsh[i];
        const int base = blockIdx.x * 8;
        #pragma unroll
        for (int r = 0; r < 8; r++) {
            int row = base + r, b = row >> 9, t = row & 511;
            srow[r][h] = (t < T_) ? s[((size_t)b * T_ + t) * SKS_ + h] : 0.0f;
        }
        __syncthreads();
        float acc[8];
        const float bias = bsh[h];
        #pragma unroll
        for (int r = 0; r < 8; r++) acc[r] = bias;
        #pragma unroll 4
        for (int k = 0; k < SKS_; k++) {
            float w = sw[h * 97 + k];
            #pragma unroll
            for (int r = 0; r < 8; r++) acc[r] = fmaf(srow[r][k], w, acc[r]);
        }
        #pragma unroll
        for (int r = 0; r < 8; r++) g_sh[(size_t)(base + r) * H_ + h] = acc[r];
    } else {
        if (blockIdx.x >= (B_ * U_) / 8) return;
        for (int i = h; i < H_ * BKS_; i += 96)
            sw[(i / BKS_) * 33 + (i % BKS_)] = Wbh[i];
        const int base = blockIdx.x * 8;
        if (h < BKS_) {
            #pragma unroll
            for (int r = 0; r < 8; r++)
                srow[r][h] = bmat[(size_t)(base + r) * BKS_ + h];
        }
        __syncthreads();
        float acc[8];
        const float bias = bbh[h];
        #pragma unroll
        for (int r = 0; r < 8; r++) acc[r] = bias;
        #pragma unroll
        for (int k = 0; k < BKS_; k++) {
            float w = sw[h * 33 + k];
            #pragma unroll
            for (int r = 0; r < 8; r++) acc[r] = fmaf(srow[r][k], w, acc[r]);
        }
        #pragma unroll
        for (int r = 0; r < 8; r++) g_rbh[(size_t)(base + r) * H_ + h] = fmaxf(acc[r], 0.0f);
    }
}

// ============================================================================
// Persistent main kernel (R6 structure). 296 CTAs (2/SM) x 256 threads.
// fp16 single-product MMA: A = fp16(z) built in registers per item,
// B = fp16(W) static in smem (LDSM), bias added in epilogue.
// Warp: mg = wid>>1 -> rows mg*32..+31, ng = wid&1 -> cols ng*64..+63.
// ============================================================================
#define S_BH  0                     // [128][PITCH] fp16 W
#define S_RED 26624                 // [128][2] float2
#define S_RBH 28672                 // [2][96] float (double-buffered)
#define S_BIA 29440                 // [128] float
#define SMEM_MAIN 30208
#define NITEMS (4 * 4 * U_)         // 7168
#define GRID_MAIN 296

__global__ __launch_bounds__(256, 2) void joiner_hmma(
    const float* __restrict__ Wout, const float* __restrict__ bout,
    float* __restrict__ out)
{
    extern __shared__ __align__(16) char smem[];
    const uint32_t sb = smem_u32(smem);
    const int tid = threadIdx.x;
    const int wid = tid >> 5, lid = tid & 31;
    const int mg = wid >> 1, ng = wid & 1;
    const int n0 = ng * 64;
    const int q  = lid >> 2, qe = lid & 3;

    // ---- one-time: stage W (fp16) + bias ----
    for (int idx = tid; idx < V_ * H_; idx += 256) {
        const int n = idx / H_, k = idx - n * H_;
        *(__half*)(smem + S_BH + n * PITCH + k * 2) = __float2half_rn(Wout[idx]);
    }
    if (tid < V_) ((float*)(smem + S_BIA))[tid] = bout[tid];

    // B ldmatrix lane addresses (proven scheme)
    const uint32_t boff = (uint32_t)(((lid & 7) + ((lid >> 4) << 3)) * PITCH + ((lid >> 3) & 1) * 16);
    const uint32_t sBh = sb + S_BH + (uint32_t)(n0 * PITCH) + boff;

    float2* red   = (float2*)(smem + S_RED);
    float*  rbAll = (float*)(smem + S_RBH);          // [2][96]
    const float* biaL = (const float*)(smem + S_BIA) + n0 + 2 * qe;

    // prologue: rbh for first item into buffer 0
    {
        const int i0 = blockIdx.x;
        if (tid < H_ && i0 < NITEMS) {
            const int u0 = i0 % U_, r20 = i0 / U_, bz0 = r20 >> 2;
            rbAll[tid] = g_rbh[((size_t)bz0 * U_ + u0) * H_ + tid];
        }
    }

    int p = 0;
    for (int item = blockIdx.x; item < NITEMS; item += GRID_MAIN, p ^= 1) {
        const int u  = item % U_;
        const int r2 = item / U_;
        const int t0 = (r2 & 3) * 128;
        const int bz = r2 >> 2;

        __syncthreads();   // rbh buffer p ready; prev item's red consumed

        // prefetch next item's rbh into a register (LDG issued early)
        float nrb = 0.0f;
        const int nitem = item + GRID_MAIN;
        if (tid < H_ && nitem < NITEMS) {
            const int nu = nitem % U_, nr2 = nitem / U_, nbz = nr2 >> 2;
            nrb = g_rbh[((size_t)nbz * U_ + nu) * H_ + tid];
        }

        const float* rbL = rbAll + p * H_ + 2 * qe;
        const float* shL = g_sh + ((size_t)(bz * TPAD) + t0 + mg * 32 + q) * H_ + 2 * qe;

        float acc[2][8][4];
        #pragma unroll
        for (int i = 0; i < 2; i++)
            #pragma unroll
            for (int j = 0; j < 8; j++)
                #pragma unroll
                for (int e4 = 0; e4 < 4; e4++) acc[i][j][e4] = 0.0f;

        // ---- 6 k-steps: A fragment in regs (fp16 of z), B via LDSM ----
        #pragma unroll
        for (int s = 0; s < 6; s++) {
            float2 rb0 = *(const float2*)(rbL + 16 * s);
            float2 rb1 = *(const float2*)(rbL + 16 * s + 8);
            uint32_t ah[2][4];
            #pragma unroll
            for (int i = 0; i < 2; i++) {
                #pragma unroll
                for (int rr = 0; rr < 2; rr++) {
                    const float* rp = shL + (i * 16 + rr * 8) * H_ + 16 * s;
                    float2 z0 = *(const float2*)(rp);
                    float2 z1 = *(const float2*)(rp + 8);
                    ah[i][rr]     = packh2(z0.x * rb0.x, z0.y * rb0.y);
                    ah[i][rr + 2] = packh2(z1.x * rb1.x, z1.y * rb1.y);
                }
            }
            uint32_t bq[4][4];
            #pragma unroll
            for (int jj = 0; jj < 4; jj++)
                LDSM4(bq[jj], sBh + jj * 16 * PITCH + s * 32);
            #pragma unroll
            for (int i = 0; i < 2; i++)
                #pragma unroll
                for (int j = 0; j < 8; j++)
                    MMA16816(acc[i][j], ah[i][0], ah[i][1], ah[i][2], ah[i][3],
                             bq[j >> 1][(j & 1) * 2], bq[j >> 1][(j & 1) * 2 + 1]);
        }

        // park next rbh into the other buffer (read next iter after sync)
        if (tid < H_ && nitem < NITEMS) rbAll[(p ^ 1) * H_ + tid] = nrb;

        // ---- bias add ----
        #pragma unroll
        for (int j = 0; j < 8; j++) {
            float2 bv = *(const float2*)(biaL + 8 * j);
            #pragma unroll
            for (int i = 0; i < 2; i++) {
                acc[i][j][0] += bv.x; acc[i][j][1] += bv.y;
                acc[i][j][2] += bv.x; acc[i][j][3] += bv.y;
            }
        }

        // ---- epilogue: log-softmax over V=128 (two warps share each row) ----
        float mx[2][2], sm[2][2];
        #pragma unroll
        for (int i = 0; i < 2; i++)
            #pragma unroll
            for (int h = 0; h < 2; h++) {
                float m = -3.4e38f;
                #pragma unroll
                for (int j = 0; j < 8; j++) {
                    m = fmaxf(m, acc[i][j][2 * h]);
                    m = fmaxf(m, acc[i][j][2 * h + 1]);
                }
                m = fmaxf(m, __shfl_xor_sync(0xffffffffu, m, 1));
                m = fmaxf(m, __shfl_xor_sync(0xffffffffu, m, 2));
                float ss = 0.0f;
                #pragma unroll
                for (int j = 0; j < 8; j++)
                    ss += __expf(acc[i][j][2 * h] - m) + __expf(acc[i][j][2 * h + 1] - m);
                ss += __shfl_xor_sync(0xffffffffu, ss, 1);
                ss += __shfl_xor_sync(0xffffffffu, ss, 2);
                mx[i][h] = m; sm[i][h] = ss;
            }
        if (qe == 0) {
            #pragma unroll
            for (int i = 0; i < 2; i++)
                #pragma unroll
                for (int h = 0; h < 2; h++)
                    red[(mg * 32 + i * 16 + h * 8 + q) * 2 + ng] = make_float2(mx[i][h], sm[i][h]);
        }
        __syncthreads();

        #pragma unroll
        for (int i = 0; i < 2; i++)
            #pragma unroll
            for (int h = 0; h < 2; h++) {
                const int rloc = i * 16 + h * 8 + q;
                const int t = t0 + mg * 32 + rloc;
                if (t >= T_) continue;
                float2 o = red[(mg * 32 + rloc) * 2 + (ng ^ 1)];
                float M = fmaxf(mx[i][h], o.x);
                float S = sm[i][h] * __expf(mx[i][h] - M) + o.y * __expf(o.x - M);
                float lse = M + __logf(S);
                float2* op = (float2*)(out + (((size_t)bz * T_ + t) * U_ + u) * V_ + n0 + qe * 2);
                #pragma unroll
                for (int j = 0; j < 8; j++) {
                    float2 v;
                    v.x = acc[i][j][2 * h]     - lse;
                    v.y = acc[i][j][2 * h + 1] - lse;
                    op[4 * j] = v;
                }
            }
    }
}

extern "C" void kernel_launch(void* const* d_in, const int* in_sizes, int n_in,
                              void* d_out, int out_size)
{
    (void)in_sizes; (void)n_in; (void)out_size;
    const float* s    = (const float*)d_in[0];
    const float* bmat = (const float*)d_in[1];
    const float* Wsh  = (const float*)d_in[2];
    const float* bsh  = (const float*)d_in[3];
    const float* Wbh  = (const float*)d_in[4];
    const float* bbh  = (const float*)d_in[5];
    const float* Wout = (const float*)d_in[6];
    const float* bout = (const float*)d_in[7];
    float* out = (float*)d_out;

    cudaFuncSetAttribute(joiner_hmma,
                         cudaFuncAttributeMaxDynamicSharedMemorySize, SMEM_MAIN);

    proj8<<<dim3((B_ * TPAD) / 8, 2), 96>>>(s, bmat, Wsh, bsh, Wbh, bbh);
    joiner_hmma<<<GRID_MAIN, 256, SMEM_MAIN>>>(Wout, bout, out);
}

// round 9
// speedup vs baseline: 1.8683x; 1.1372x over previous
#include <cuda_runtime.h>
#include <cuda_fp16.h>
#include <cstdint>
#include <cstddef>

#define B_   4
#define T_   448
#define TPAD 512
#define U_   448
#define SKS_ 96
#define BKS_ 32
#define H_   96
#define V_   128
#define PITCH 208          // B smem row pitch (96 fp16 + pad)
#define APITCH 400         // sh smem row pitch bytes (100 floats) -> degree-2 LDS

// ---------------- device scratch ----------------
__device__ float g_sh [B_ * TPAD * H_];
__device__ float g_rbh[B_ * U_ * H_];

// ---------------- asm helpers ----------------
__device__ __forceinline__ uint32_t smem_u32(const void* p) {
    uint32_t a;
    asm("{ .reg .u64 t; cvta.to.shared.u64 t, %1; cvt.u32.u64 %0, t; }" : "=r"(a) : "l"(p));
    return a;
}
#define LDSM4(r, addr) \
    asm volatile("ldmatrix.sync.aligned.m8n8.x4.shared.b16 {%0,%1,%2,%3}, [%4];" \
        : "=r"((r)[0]), "=r"((r)[1]), "=r"((r)[2]), "=r"((r)[3]) : "r"(addr))

#define MMA16816(c, a0, a1, a2, a3, b0, b1) \
    asm volatile("mma.sync.aligned.m16n8k16.row.col.f32.f16.f16.f32 " \
        "{%0,%1,%2,%3}, {%4,%5,%6,%7}, {%8,%9}, {%0,%1,%2,%3};" \
        : "+f"((c)[0]), "+f"((c)[1]), "+f"((c)[2]), "+f"((c)[3]) \
        : "r"(a0), "r"(a1), "r"(a2), "r"(a3), "r"(b0), "r"(b1))

__device__ __forceinline__ uint32_t packh2(float a, float b) {
    __half2 h = __floats2half2_rn(a, b);
    return *reinterpret_cast<uint32_t*>(&h);
}

// ============================================================================
// Input projections (unchanged from R8).
// ============================================================================
__global__ __launch_bounds__(96) void proj8(
    const float* __restrict__ s,   const float* __restrict__ bmat,
    const float* __restrict__ Wsh, const float* __restrict__ bsh,
    const float* __restrict__ Wbh, const float* __restrict__ bbh)
{
    __shared__ float sw[H_ * 97];
    __shared__ float srow[8][97];
    const int h = threadIdx.x;

    if (blockIdx.y == 0) {
        for (int i = h; i < H_ * SKS_; i += 96)
            sw[(i / SKS_) * 97 + (i % SKS_)] = Wsh[i];
        const int base = blockIdx.x * 8;
        #pragma unroll
        for (int r = 0; r < 8; r++) {
            int row = base + r, b = row >> 9, t = row & 511;
            srow[r][h] = (t < T_) ? s[((size_t)b * T_ + t) * SKS_ + h] : 0.0f;
        }
        __syncthreads();
        float acc[8];
        const float bias = bsh[h];
        #pragma unroll
        for (int r = 0; r < 8; r++) acc[r] = bias;
        #pragma unroll 4
        for (int k = 0; k < SKS_; k++) {
            float w = sw[h * 97 + k];
            #pragma unroll
            for (int r = 0; r < 8; r++) acc[r] = fmaf(srow[r][k], w, acc[r]);
        }
        #pragma unroll
        for (int r = 0; r < 8; r++) g_sh[(size_t)(base + r) * H_ + h] = acc[r];
    } else {
        if (blockIdx.x >= (B_ * U_) / 8) return;
        for (int i = h; i < H_ * BKS_; i += 96)
            sw[(i / BKS_) * 33 + (i % BKS_)] = Wbh[i];
        const int base = blockIdx.x * 8;
        if (h < BKS_) {
            #pragma unroll
            for (int r = 0; r < 8; r++)
                srow[r][h] = bmat[(size_t)(base + r) * BKS_ + h];
        }
        __syncthreads();
        float acc[8];
        const float bias = bbh[h];
        #pragma unroll
        for (int r = 0; r < 8; r++) acc[r] = bias;
        #pragma unroll
        for (int k = 0; k < BKS_; k++) {
            float w = sw[h * 33 + k];
            #pragma unroll
            for (int r = 0; r < 8; r++) acc[r] = fmaf(srow[r][k], w, acc[r]);
        }
        #pragma unroll
        for (int r = 0; r < 8; r++) g_rbh[(size_t)(base + r) * H_ + h] = fmaxf(acc[r], 0.0f);
    }
}

// ============================================================================
// Main kernel. grid (18, 16): y = (bz, t0) group, x = u-chunk (~25 u's).
// Per CTA, staged ONCE: W fp16 (LDSM operand), sh tile fp32 [128][100].
// Per item: rbh (double-buffered w/ reg prefetch), A frags via cheap LDS,
// B via LDSM, fp16 single-product MMA, bias+log-softmax epilogue.
// Warp: mg = wid>>1 -> rows mg*32..+31, ng = wid&1 -> cols ng*64..+63.
// ============================================================================
#define S_BH  0                     // [128][PITCH] fp16 W
#define S_SH  26624                 // [128][APITCH] fp32 sh tile
#define S_RED 77824                 // [128][2] float2
#define S_RBH 79872                 // [2][96] float
#define S_BIA 80640                 // [128] float
#define SMEM_MAIN 81152

__global__ __launch_bounds__(256, 2) void joiner_hmma(
    const float* __restrict__ Wout, const float* __restrict__ bout,
    float* __restrict__ out)
{
    extern __shared__ __align__(16) char smem[];
    const uint32_t sb = smem_u32(smem);
    const int tid = threadIdx.x;
    const int wid = tid >> 5, lid = tid & 31;
    const int mg = wid >> 1, ng = wid & 1;
    const int n0 = ng * 64;
    const int q  = lid >> 2, qe = lid & 3;

    const int g  = blockIdx.y;
    const int t0 = (g & 3) * 128;
    const int bz = g >> 2;
    const int c  = blockIdx.x;                       // 0..17
    const int ustart = c * 24 + (c < 16 ? c : 16);
    const int ucnt   = 24 + (c < 16 ? 1 : 0);

    // ---- one-time: stage W (fp16), bias, and the sh fp32 tile ----
    for (int idx = tid; idx < V_ * H_; idx += 256) {
        const int n = idx / H_, k = idx - n * H_;
        *(__half*)(smem + S_BH + n * PITCH + k * 2) = __float2half_rn(Wout[idx]);
    }
    if (tid < V_) ((float*)(smem + S_BIA))[tid] = bout[tid];
    {
        const float4* src = (const float4*)(g_sh + ((size_t)(bz * TPAD) + t0) * H_);
        for (int i = tid; i < 128 * 24; i += 256) {
            const int row = i / 24, kq = i - row * 24;
            *(float4*)(smem + S_SH + row * APITCH + kq * 16) = src[row * 24 + kq];
        }
    }

    // lane addresses
    const uint32_t boff = (uint32_t)(((lid & 7) + ((lid >> 4) << 3)) * PITCH + ((lid >> 3) & 1) * 16);
    const uint32_t sBh = sb + S_BH + (uint32_t)(n0 * PITCH) + boff;
    const char* shS = smem + S_SH + (mg * 32 + q) * APITCH + qe * 8;

    float2* red   = (float2*)(smem + S_RED);
    float*  rbAll = (float*)(smem + S_RBH);
    const float* biaL = (const float*)(smem + S_BIA) + n0 + 2 * qe;

    // prologue: rbh for first item into buffer 0
    if (tid < H_) rbAll[tid] = g_rbh[((size_t)bz * U_ + ustart) * H_ + tid];

    int p = 0;
    for (int it = 0; it < ucnt; it++, p ^= 1) {
        const int u = ustart + it;

        __syncthreads();   // rbh buffer p + sh tile ready; prev red consumed

        // prefetch next item's rbh into a register
        float nrb = 0.0f;
        if (tid < H_ && it + 1 < ucnt)
            nrb = g_rbh[((size_t)bz * U_ + u + 1) * H_ + tid];

        const float* rbL = rbAll + p * H_ + 2 * qe;

        float acc[2][8][4];
        #pragma unroll
        for (int i = 0; i < 2; i++)
            #pragma unroll
            for (int j = 0; j < 8; j++)
                #pragma unroll
                for (int e4 = 0; e4 < 4; e4++) acc[i][j][e4] = 0.0f;

        // ---- 6 k-steps: A fragment from smem sh * rbh, B via LDSM ----
        #pragma unroll
        for (int s = 0; s < 6; s++) {
            float2 rb0 = *(const float2*)(rbL + 16 * s);
            float2 rb1 = *(const float2*)(rbL + 16 * s + 8);
            uint32_t ah[2][4];
            #pragma unroll
            for (int i = 0; i < 2; i++) {
                #pragma unroll
                for (int rr = 0; rr < 2; rr++) {
                    const char* rp = shS + (i * 16 + rr * 8) * APITCH + s * 64;
                    float2 z0 = *(const float2*)(rp);
                    float2 z1 = *(const float2*)(rp + 32);
                    ah[i][rr]     = packh2(z0.x * rb0.x, z0.y * rb0.y);
                    ah[i][rr + 2] = packh2(z1.x * rb1.x, z1.y * rb1.y);
                }
            }
            uint32_t bq[4][4];
            #pragma unroll
            for (int jj = 0; jj < 4; jj++)
                LDSM4(bq[jj], sBh + jj * 16 * PITCH + s * 32);
            #pragma unroll
            for (int i = 0; i < 2; i++)
                #pragma unroll
                for (int j = 0; j < 8; j++)
                    MMA16816(acc[i][j], ah[i][0], ah[i][1], ah[i][2], ah[i][3],
                             bq[j >> 1][(j & 1) * 2], bq[j >> 1][(j & 1) * 2 + 1]);
        }

        // park next rbh into the other buffer
        if (tid < H_ && it + 1 < ucnt) rbAll[(p ^ 1) * H_ + tid] = nrb;

        // ---- bias add ----
        #pragma unroll
        for (int j = 0; j < 8; j++) {
            float2 bv = *(const float2*)(biaL + 8 * j);
            #pragma unroll
            for (int i = 0; i < 2; i++) {
                acc[i][j][0] += bv.x; acc[i][j][1] += bv.y;
                acc[i][j][2] += bv.x; acc[i][j][3] += bv.y;
            }
        }

        // ---- epilogue: log-softmax over V=128 (two warps share each row) ----
        float mx[2][2], sm[2][2];
        #pragma unroll
        for (int i = 0; i < 2; i++)
            #pragma unroll
            for (int h = 0; h < 2; h++) {
                float m = -3.4e38f;
                #pragma unroll
                for (int j = 0; j < 8; j++) {
                    m = fmaxf(m, acc[i][j][2 * h]);
                    m = fmaxf(m, acc[i][j][2 * h + 1]);
                }
                m = fmaxf(m, __shfl_xor_sync(0xffffffffu, m, 1));
                m = fmaxf(m, __shfl_xor_sync(0xffffffffu, m, 2));
                float ss = 0.0f;
                #pragma unroll
                for (int j = 0; j < 8; j++)
                    ss += __expf(acc[i][j][2 * h] - m) + __expf(acc[i][j][2 * h + 1] - m);
                ss += __shfl_xor_sync(0xffffffffu, ss, 1);
                ss += __shfl_xor_sync(0xffffffffu, ss, 2);
                mx[i][h] = m; sm[i][h] = ss;
            }
        if (qe == 0) {
            #pragma unroll
            for (int i = 0; i < 2; i++)
                #pragma unroll
                for (int h = 0; h < 2; h++)
                    red[(mg * 32 + i * 16 + h * 8 + q) * 2 + ng] = make_float2(mx[i][h], sm[i][h]);
        }
        __syncthreads();

        #pragma unroll
        for (int i = 0; i < 2; i++)
            #pragma unroll
            for (int h = 0; h < 2; h++) {
                const int rloc = i * 16 + h * 8 + q;
                const int t = t0 + mg * 32 + rloc;
                if (t >= T_) continue;
                float2 o = red[(mg * 32 + rloc) * 2 + (ng ^ 1)];
                float M = fmaxf(mx[i][h], o.x);
                float S = sm[i][h] * __expf(mx[i][h] - M) + o.y * __expf(o.x - M);
                float lse = M + __logf(S);
                float2* op = (float2*)(out + (((size_t)bz * T_ + t) * U_ + u) * V_ + n0 + qe * 2);
                #pragma unroll
                for (int j = 0; j < 8; j++) {
                    float2 v;
                    v.x = acc[i][j][2 * h]     - lse;
                    v.y = acc[i][j][2 * h + 1] - lse;
                    op[4 * j] = v;
                }
            }
    }
}

extern "C" void kernel_launch(void* const* d_in, const int* in_sizes, int n_in,
                              void* d_out, int out_size)
{
    (void)in_sizes; (void)n_in; (void)out_size;
    const float* s    = (const float*)d_in[0];
    const float* bmat = (const float*)d_in[1];
    const float* Wsh  = (const float*)d_in[2];
    const float* bsh  = (const float*)d_in[3];
    const float* Wbh  = (const float*)d_in[4];
    const float* bbh  = (const float*)d_in[5];
    const float* Wout = (const float*)d_in[6];
    const float* bout = (const float*)d_in[7];
    float* out = (float*)d_out;

    cudaFuncSetAttribute(joiner_hmma,
                         cudaFuncAttributeMaxDynamicSharedMemorySize, SMEM_MAIN);

    proj8<<<dim3((B_ * TPAD) / 8, 2), 96>>>(s, bmat, Wsh, bsh, Wbh, bbh);
    joiner_hmma<<<dim3(18, 16), 256, SMEM_MAIN>>>(Wout, bout, out);
}

// round 10
// speedup vs baseline: 2.2516x; 1.2052x over previous
#include <cuda_runtime.h>
#include <cuda_fp16.h>
#include <cstdint>
#include <cstddef>

#define B_   4
#define T_   448
#define TPAD 512
#define U_   448
#define SKS_ 96
#define BKS_ 32
#define H_   96
#define V_   128
#define PITCH 208          // smem row pitch (96 fp16 = 192 B + pad) -> conflict-free ldmatrix

// ---------------- device scratch (fp16) ----------------
__device__ __align__(16) unsigned short g_shh [B_ * TPAD * H_];  // fp16 sh
__device__ __align__(16) unsigned short g_rbhh[B_ * U_ * H_];    // fp16 relu(bh)

// ---------------- asm helpers ----------------
__device__ __forceinline__ uint32_t smem_u32(const void* p) {
    uint32_t a;
    asm("{ .reg .u64 t; cvta.to.shared.u64 t, %1; cvt.u32.u64 %0, t; }" : "=r"(a) : "l"(p));
    return a;
}
#define LDSM4(r, addr) \
    asm volatile("ldmatrix.sync.aligned.m8n8.x4.shared.b16 {%0,%1,%2,%3}, [%4];" \
        : "=r"((r)[0]), "=r"((r)[1]), "=r"((r)[2]), "=r"((r)[3]) : "r"(addr))

#define MMA16816(c, a0, a1, a2, a3, b0, b1) \
    asm volatile("mma.sync.aligned.m16n8k16.row.col.f32.f16.f16.f32 " \
        "{%0,%1,%2,%3}, {%4,%5,%6,%7}, {%8,%9}, {%0,%1,%2,%3};" \
        : "+f"((c)[0]), "+f"((c)[1]), "+f"((c)[2]), "+f"((c)[3]) \
        : "r"(a0), "r"(a1), "r"(a2), "r"(a3), "r"(b0), "r"(b1))

__device__ __forceinline__ uint32_t hmul2u(uint32_t a, uint32_t b) {
    __half2 r = __hmul2(*reinterpret_cast<__half2*>(&a), *reinterpret_cast<__half2*>(&b));
    return *reinterpret_cast<uint32_t*>(&r);
}

// ============================================================================
// Input projections; outputs stored as fp16.
// ============================================================================
__global__ __launch_bounds__(96) void proj8(
    const float* __restrict__ s,   const float* __restrict__ bmat,
    const float* __restrict__ Wsh, const float* __restrict__ bsh,
    const float* __restrict__ Wbh, const float* __restrict__ bbh)
{
    __shared__ float sw[H_ * 97];
    __shared__ float srow[8][97];
    const int h = threadIdx.x;

    if (blockIdx.y == 0) {
        for (int i = h; i < H_ * SKS_; i += 96)
            sw[(i / SKS_) * 97 + (i % SKS_)] = Wsh[i];
        const int base = blockIdx.x * 8;
        #pragma unroll
        for (int r = 0; r < 8; r++) {
            int row = base + r, b = row >> 9, t = row & 511;
            srow[r][h] = (t < T_) ? s[((size_t)b * T_ + t) * SKS_ + h] : 0.0f;
        }
        __syncthreads();
        float acc[8];
        const float bias = bsh[h];
        #pragma unroll
        for (int r = 0; r < 8; r++) acc[r] = bias;
        #pragma unroll 4
        for (int k = 0; k < SKS_; k++) {
            float w = sw[h * 97 + k];
            #pragma unroll
            for (int r = 0; r < 8; r++) acc[r] = fmaf(srow[r][k], w, acc[r]);
        }
        #pragma unroll
        for (int r = 0; r < 8; r++) {
            __half v = __float2half_rn(acc[r]);
            g_shh[(size_t)(base + r) * H_ + h] = *reinterpret_cast<unsigned short*>(&v);
        }
    } else {
        if (blockIdx.x >= (B_ * U_) / 8) return;
        for (int i = h; i < H_ * BKS_; i += 96)
            sw[(i / BKS_) * 33 + (i % BKS_)] = Wbh[i];
        const int base = blockIdx.x * 8;
        if (h < BKS_) {
            #pragma unroll
            for (int r = 0; r < 8; r++)
                srow[r][h] = bmat[(size_t)(base + r) * BKS_ + h];
        }
        __syncthreads();
        float acc[8];
        const float bias = bbh[h];
        #pragma unroll
        for (int r = 0; r < 8; r++) acc[r] = bias;
        #pragma unroll
        for (int k = 0; k < BKS_; k++) {
            float w = sw[h * 33 + k];
            #pragma unroll
            for (int r = 0; r < 8; r++) acc[r] = fmaf(srow[r][k], w, acc[r]);
        }
        #pragma unroll
        for (int r = 0; r < 8; r++) {
            __half v = __float2half_rn(fmaxf(acc[r], 0.0f));
            g_rbhh[(size_t)(base + r) * H_ + h] = *reinterpret_cast<unsigned short*>(&v);
        }
    }
}

// ============================================================================
// Main kernel. grid (18, 16): y = (bz, t0) group, x = u-chunk (~25 u's).
// Staged once per CTA: W fp16, sh fp16 tile (both LDSM operands), bias.
// Per item: rbh half2 (double-buffered, reg-prefetch); A frag = LDSM(sh) then
// HMUL2 by rbh; B via LDSM; fp16 MMA; bias + log-softmax epilogue.
// Warp: mg = wid>>1 -> rows mg*32..+31, ng = wid&1 -> cols ng*64..+63.
// ============================================================================
#define S_BH   0                    // [128][PITCH] fp16 W
#define S_SHH  26624                // [128][PITCH] fp16 sh tile
#define S_RED  53248                // [128][2] float2
#define S_RBH  55296                // [2][48] uint (half2 rbh)
#define S_BIA  55680                // [128] float
#define SMEM_MAIN 56192

__global__ __launch_bounds__(256, 2) void joiner_hmma(
    const float* __restrict__ Wout, const float* __restrict__ bout,
    float* __restrict__ out)
{
    extern __shared__ __align__(16) char smem[];
    const uint32_t sb = smem_u32(smem);
    const int tid = threadIdx.x;
    const int wid = tid >> 5, lid = tid & 31;
    const int mg = wid >> 1, ng = wid & 1;
    const int n0 = ng * 64;
    const int q  = lid >> 2, qe = lid & 3;

    const int g  = blockIdx.y;
    const int t0 = (g & 3) * 128;
    const int bz = g >> 2;
    const int c  = blockIdx.x;                       // 0..17
    const int ustart = c * 24 + (c < 16 ? c : 16);
    const int ucnt   = 24 + (c < 16 ? 1 : 0);

    // ---- one-time: stage W (fp16), bias, sh fp16 tile ----
    for (int idx = tid; idx < V_ * H_; idx += 256) {
        const int n = idx / H_, k = idx - n * H_;
        *(__half*)(smem + S_BH + n * PITCH + k * 2) = __float2half_rn(Wout[idx]);
    }
    if (tid < V_) ((float*)(smem + S_BIA))[tid] = bout[tid];
    {
        const uint4* src = (const uint4*)(g_shh + ((size_t)(bz * TPAD) + t0) * H_);
        for (int i = tid; i < 128 * 12; i += 256) {
            const int row = i / 12, kq = i - row * 12;
            *(uint4*)(smem + S_SHH + row * PITCH + kq * 16) = src[row * 12 + kq];
        }
    }

    // ldmatrix lane addresses (A and B use the same proven pitch scheme)
    const uint32_t aoff = (uint32_t)((lid & 15) * PITCH + (lid >> 4) * 16);
    const uint32_t boff = (uint32_t)(((lid & 7) + ((lid >> 4) << 3)) * PITCH + ((lid >> 3) & 1) * 16);
    const uint32_t sAh = sb + S_SHH + (uint32_t)(mg * 32 * PITCH) + aoff;
    const uint32_t sBh = sb + S_BH + (uint32_t)(n0 * PITCH) + boff;

    float2*   red   = (float2*)(smem + S_RED);
    uint32_t* rbAll = (uint32_t*)(smem + S_RBH);     // [2][48] half2
    const float* biaL = (const float*)(smem + S_BIA) + n0 + 2 * qe;

    // prologue: rbh for first item into buffer 0
    if (tid < 48)
        rbAll[tid] = ((const uint32_t*)(g_rbhh + ((size_t)bz * U_ + ustart) * H_))[tid];

    int p = 0;
    for (int it = 0; it < ucnt; it++, p ^= 1) {
        const int u = ustart + it;

        __syncthreads();   // rbh buffer p + tiles ready; prev red consumed

        // prefetch next item's rbh (half2) into a register
        uint32_t nrb = 0u;
        if (tid < 48 && it + 1 < ucnt)
            nrb = ((const uint32_t*)(g_rbhh + ((size_t)bz * U_ + u + 1) * H_))[tid];

        const char* rbB = (const char*)(rbAll + p * 48);

        float acc[2][8][4];
        #pragma unroll
        for (int i = 0; i < 2; i++)
            #pragma unroll
            for (int j = 0; j < 8; j++)
                #pragma unroll
                for (int e4 = 0; e4 < 4; e4++) acc[i][j][e4] = 0.0f;

        // ---- 6 k-steps: A = LDSM(sh) * rbh (HMUL2), B via LDSM ----
        #pragma unroll
        for (int s = 0; s < 6; s++) {
            uint32_t rb0 = *(const uint32_t*)(rbB + s * 32 + qe * 4);        // cols 2qe
            uint32_t rb1 = *(const uint32_t*)(rbB + s * 32 + 16 + qe * 4);   // cols 8+2qe
            uint32_t am[2][4], ah[2][4], bq[4][4];
            #pragma unroll
            for (int i = 0; i < 2; i++) {
                LDSM4(am[i], sAh + i * 16 * PITCH + s * 32);
                ah[i][0] = hmul2u(am[i][0], rb0);
                ah[i][1] = hmul2u(am[i][1], rb0);
                ah[i][2] = hmul2u(am[i][2], rb1);
                ah[i][3] = hmul2u(am[i][3], rb1);
            }
            #pragma unroll
            for (int jj = 0; jj < 4; jj++)
                LDSM4(bq[jj], sBh + jj * 16 * PITCH + s * 32);
            #pragma unroll
            for (int i = 0; i < 2; i++)
                #pragma unroll
                for (int j = 0; j < 8; j++)
                    MMA16816(acc[i][j], ah[i][0], ah[i][1], ah[i][2], ah[i][3],
                             bq[j >> 1][(j & 1) * 2], bq[j >> 1][(j & 1) * 2 + 1]);
        }

        // park next rbh into the other buffer
        if (tid < 48 && it + 1 < ucnt) rbAll[(p ^ 1) * 48 + tid] = nrb;

        // ---- bias add ----
        #pragma unroll
        for (int j = 0; j < 8; j++) {
            float2 bv = *(const float2*)(biaL + 8 * j);
            #pragma unroll
            for (int i = 0; i < 2; i++) {
                acc[i][j][0] += bv.x; acc[i][j][1] += bv.y;
                acc[i][j][2] += bv.x; acc[i][j][3] += bv.y;
            }
        }

        // ---- epilogue: log-softmax over V=128 (two warps share each row) ----
        float mx[2][2], sm[2][2];
        #pragma unroll
        for (int i = 0; i < 2; i++)
            #pragma unroll
            for (int h = 0; h < 2; h++) {
                float m = -3.4e38f;
                #pragma unroll
                for (int j = 0; j < 8; j++) {
                    m = fmaxf(m, acc[i][j][2 * h]);
                    m = fmaxf(m, acc[i][j][2 * h + 1]);
                }
                m = fmaxf(m, __shfl_xor_sync(0xffffffffu, m, 1));
                m = fmaxf(m, __shfl_xor_sync(0xffffffffu, m, 2));
                float ss = 0.0f;
                #pragma unroll
                for (int j = 0; j < 8; j++)
                    ss += __expf(acc[i][j][2 * h] - m) + __expf(acc[i][j][2 * h + 1] - m);
                ss += __shfl_xor_sync(0xffffffffu, ss, 1);
                ss += __shfl_xor_sync(0xffffffffu, ss, 2);
                mx[i][h] = m; sm[i][h] = ss;
            }
        if (qe == 0) {
            #pragma unroll
            for (int i = 0; i < 2; i++)
                #pragma unroll
                for (int h = 0; h < 2; h++)
                    red[(mg * 32 + i * 16 + h * 8 + q) * 2 + ng] = make_float2(mx[i][h], sm[i][h]);
        }
        __syncthreads();

        #pragma unroll
        for (int i = 0; i < 2; i++)
            #pragma unroll
            for (int h = 0; h < 2; h++) {
                const int rloc = i * 16 + h * 8 + q;
                const int t = t0 + mg * 32 + rloc;
                if (t >= T_) continue;
                float2 o = red[(mg * 32 + rloc) * 2 + (ng ^ 1)];
                float M = fmaxf(mx[i][h], o.x);
                float S = sm[i][h] * __expf(mx[i][h] - M) + o.y * __expf(o.x - M);
                float lse = M + __logf(S);
                float2* op = (float2*)(out + (((size_t)bz * T_ + t) * U_ + u) * V_ + n0 + qe * 2);
                #pragma unroll
                for (int j = 0; j < 8; j++) {
                    float2 v;
                    v.x = acc[i][j][2 * h]     - lse;
                    v.y = acc[i][j][2 * h + 1] - lse;
                    op[4 * j] = v;
                }
            }
    }
}

extern "C" void kernel_launch(void* const* d_in, const int* in_sizes, int n_in,
                              void* d_out, int out_size)
{
    (void)in_sizes; (void)n_in; (void)out_size;
    const float* s    = (const float*)d_in[0];
    const float* bmat = (const float*)d_in[1];
    const float* Wsh  = (const float*)d_in[2];
    const float* bsh  = (const float*)d_in[3];
    const float* Wbh  = (const float*)d_in[4];
    const float* bbh  = (const float*)d_in[5];
    const float* Wout = (const float*)d_in[6];
    const float* bout = (const float*)d_in[7];
    float* out = (float*)d_out;

    cudaFuncSetAttribute(joiner_hmma,
                         cudaFuncAttributeMaxDynamicSharedMemorySize, SMEM_MAIN);

    proj8<<<dim3((B_ * TPAD) / 8, 2), 96>>>(s, bmat, Wsh, bsh, Wbh, bbh);
    joiner_hmma<<<dim3(18, 16), 256, SMEM_MAIN>>>(Wout, bout, out);
}